// round 5
// baseline (speedup 1.0000x reference)
#include <cuda_runtime.h>
#include <cooperative_groups.h>
#include <math.h>

namespace cg = cooperative_groups;

#define Mdim 512
#define Ndim 2048
#define Bsz  4
#define Lnum 20
#define CAP  24576            // global nnz cap (E[nnz]=20971)
#define LCAP 6656             // per-CTA (128-row) entry cap
#define ROWCAP 96             // per-row entry cap
#define MNdim (Mdim*Ndim)
#define EPSV 1e-6f
#define NTH  1024
#define CLSZ 4
#define ROWS_PER_CTA (Mdim/CLSZ)   // 128
#define COLS_PER_CTA (Ndim/CLSZ)   // 512

// ---------------- device scratch ----------------
__device__ int            g_deg[Mdim];
__device__ int            g_rowptr[Mdim + 1];
__device__ int            g_nnz;
__device__ unsigned short g_stage[Mdim * ROWCAP];
__device__ unsigned       g_lin[CAP];        // CSR (row-major) linear indices
__device__ unsigned short g_perm[CAP];       // CSC pos -> local CSR pos (per slice)
__device__ unsigned       g_linC[CAP];       // CSC-ordered linear indices
__device__ unsigned char  g_rowC[CAP];       // CSC-ordered local row index
__device__ int            g_colptr[CLSZ * (Ndim + 1)];
__device__ float          g_wdeC[Lnum * CAP];   // weights_de, CSC order per slice
__device__ float          g_mwdeC[Lnum * CAP];  // marg_weights_de, CSC order per slice
__device__ float          g_rho[Lnum];

// ---------------- P1: block per row — degree + staged column list ----------------
__global__ void k_prep1(const float4* __restrict__ H4) {
    __shared__ int s_cnt;
    __shared__ unsigned short s_cols[ROWCAP];
    const int i = blockIdx.x;
    const int t = threadIdx.x;       // 512 threads, one float4 each
    const int lane = t & 31;
    if (t == 0) s_cnt = 0;
    __syncthreads();
    float4 v = H4[(size_t)i * (Ndim / 4) + t];
    int cnt = (v.x != 0.0f) + (v.y != 0.0f) + (v.z != 0.0f) + (v.w != 0.0f);
    int sc = cnt;
    for (int o = 1; o < 32; o <<= 1) {
        int u = __shfl_up_sync(0xffffffffu, sc, o);
        if (lane >= o) sc += u;
    }
    int total = __shfl_sync(0xffffffffu, sc, 31);
    int base = 0;
    if (lane == 31 && total) base = atomicAdd(&s_cnt, total);
    base = __shfl_sync(0xffffffffu, base, 31);
    int idx = base + sc - cnt;
    int c = t * 4;
    if (v.x != 0.0f && idx < ROWCAP) s_cols[idx++] = (unsigned short)c;
    if (v.y != 0.0f && idx < ROWCAP) s_cols[idx++] = (unsigned short)(c + 1);
    if (v.z != 0.0f && idx < ROWCAP) s_cols[idx++] = (unsigned short)(c + 2);
    if (v.w != 0.0f && idx < ROWCAP) s_cols[idx++] = (unsigned short)(c + 3);
    __syncthreads();
    int d = min(s_cnt, ROWCAP);
    if (t == 0) g_deg[i] = d;
    if (t < d) g_stage[i * ROWCAP + t] = s_cols[t];
}

// ---------------- P2: scan + expand CSR + softmax + zero out ----------------
__global__ void k_prep2(const float* __restrict__ rhos, float* __restrict__ out) {
    __shared__ int s[Mdim];
    const int t = threadIdx.x;
    s[t] = g_deg[t];
    __syncthreads();
    for (int off = 1; off < Mdim; off <<= 1) {
        int v = (t >= off) ? s[t - off] : 0;
        __syncthreads();
        s[t] += v;
        __syncthreads();
    }
    g_rowptr[t + 1] = s[t];
    if (t == 0) g_rowptr[0] = 0;
    if (t == Mdim - 1) g_nnz = s[Mdim - 1];
    int st = s[t] - g_deg[t];
    int d  = g_deg[t];
    unsigned lbase = (unsigned)(t * Ndim);
    for (int k = 0; k < d; k++) {
        int idx = st + k;
        if (idx < CAP) g_lin[idx] = lbase + g_stage[t * ROWCAP + k];
    }
    if (t == 0) {
        *out = 0.0f;
        float mx = -1e30f;
        for (int l = 0; l < Lnum; l++) mx = fmaxf(mx, rhos[l]);
        float e[Lnum], sm = 0.0f;
        for (int l = 0; l < Lnum; l++) { e[l] = expf(rhos[l] - mx); sm += e[l]; }
        float inv = 1.0f / sm;
        for (int l = 0; l < Lnum; l++) g_rho[l] = e[l] * inv;
    }
}

// ---------------- P3: per-slice CSC (colptr + perm + linC + rowC) ----------------
__global__ void k_prep3() {
    __shared__ int s_hist[Ndim];     // counts, then cursors
    __shared__ int s_cp[Ndim + 1];
    __shared__ int s_wsum[32];
    const int blk = blockIdx.x;
    const int t = threadIdx.x;
    const int lane = t & 31;
    const int wid = t >> 5;
    const int r0 = blk * ROWS_PER_CTA;
    const int kbase = g_rowptr[r0];
    int kend = g_rowptr[r0 + ROWS_PER_CTA];
    if (kend - kbase > LCAP) kend = kbase + LCAP;
    const int cnt = kend - kbase;

    s_hist[t] = 0; s_hist[t + 1024] = 0;
    __syncthreads();
    for (int k = t; k < cnt; k += 1024)
        atomicAdd(&s_hist[g_lin[kbase + k] & (Ndim - 1)], 1);
    __syncthreads();
    int a = s_hist[2 * t], b = s_hist[2 * t + 1];
    int ssum = a + b;
    int sc = ssum;
    for (int o = 1; o < 32; o <<= 1) {
        int u = __shfl_up_sync(0xffffffffu, sc, o);
        if (lane >= o) sc += u;
    }
    if (lane == 31) s_wsum[wid] = sc;
    __syncthreads();
    if (wid == 0) {
        int v = s_wsum[lane];
        for (int o = 1; o < 32; o <<= 1) {
            int u = __shfl_up_sync(0xffffffffu, v, o);
            if (lane >= o) v += u;
        }
        s_wsum[lane] = v;
    }
    __syncthreads();
    int incl = sc + ((wid > 0) ? s_wsum[wid - 1] : 0);
    int excl = incl - ssum;
    s_cp[2 * t] = excl;
    s_cp[2 * t + 1] = excl + a;
    if (t == 1023) s_cp[Ndim] = incl;
    __syncthreads();
    s_hist[2 * t] = s_cp[2 * t];
    s_hist[2 * t + 1] = s_cp[2 * t + 1];
    g_colptr[blk * (Ndim + 1) + 2 * t]     = s_cp[2 * t];
    g_colptr[blk * (Ndim + 1) + 2 * t + 1] = s_cp[2 * t + 1];
    if (t == 1023) g_colptr[blk * (Ndim + 1) + Ndim] = s_cp[Ndim];
    __syncthreads();
    for (int k = t; k < cnt; k += 1024) {
        unsigned lin = g_lin[kbase + k];
        int j = lin & (Ndim - 1);
        int pos = atomicAdd(&s_hist[j], 1);
        g_perm[kbase + pos] = (unsigned short)k;
        g_linC[kbase + pos] = lin;
        g_rowC[kbase + pos] = (unsigned char)((lin >> 11) - r0);
    }
}

// ---------------- P4: gather dense weights at nonzeros, CSC order ----------------
__global__ void k_gather(const float* __restrict__ wde, const float* __restrict__ mwde) {
    int nnz = min(g_nnz, CAP);
    int idx = blockIdx.x * blockDim.x + threadIdx.x;
    if (idx >= Lnum * CAP) return;
    int l = idx / CAP;
    int p = idx - l * CAP;
    if (p >= nnz) return;
    size_t off = (size_t)l * MNdim + g_linC[p];
    g_wdeC[idx]  = wde[off];
    g_mwdeC[idx] = mwde[off];
}

// ---------------- main BP recurrence (single cluster.sync per layer) ----------------
// floats: msgs LCAP | d LCAP | colC N | colP 2N | belP 2N | rp R | sign2 R | offf R |
//         err C | resw 32 | rho 32 | lacc 32 ; int rpt R+4 ;
// u16: lin LCAP | perm LCAP | cptr N+4 ; u8: rowC LCAP
#define SMEM_BYTES ((2*LCAP + 5*Ndim + 3*ROWS_PER_CTA + COLS_PER_CTA + 96 \
                     + (ROWS_PER_CTA + 4)) * 4 + (2*LCAP + Ndim + 4) * 2 + LCAP)

__global__ void __launch_bounds__(NTH, 1) __cluster_dims__(CLSZ, 1, 1)
k_main(const int*   __restrict__ synd,
       const int*   __restrict__ errs,
       const float* __restrict__ llrs,
       const float* __restrict__ wllr,
       const float* __restrict__ mwllr,
       const float* __restrict__ resw,
       float* __restrict__ out)
{
    extern __shared__ char sm_raw[];
    float* s_msgs  = (float*)sm_raw;                 // LCAP
    float* s_d     = s_msgs + LCAP;                  // LCAP
    float* s_colC  = s_d + LCAP;                     // N
    float* s_colP  = s_colC + Ndim;                  // 2N (parity buffers)
    float* s_belP  = s_colP + 2 * Ndim;              // 2N
    float* s_rp    = s_belP + 2 * Ndim;              // R
    float* s_sign2 = s_rp + ROWS_PER_CTA;            // R
    float* s_offf  = s_sign2 + ROWS_PER_CTA;         // R
    float* s_err   = s_offf + ROWS_PER_CTA;          // C
    float* s_resw  = s_err + COLS_PER_CTA;           // 32
    float* s_rho   = s_resw + 32;                    // 32
    float* s_lacc  = s_rho + 32;                     // 32
    int*   s_rpt   = (int*)(s_lacc + 32);            // R+1 (+pad)
    unsigned short* s_lin  = (unsigned short*)(s_rpt + ROWS_PER_CTA + 4);  // LCAP
    unsigned short* s_perm = s_lin + LCAP;                                  // LCAP
    unsigned short* s_cptr = s_perm + LCAP;                                 // N+1 (+pad)
    unsigned char*  s_rowC = (unsigned char*)(s_cptr + Ndim + 4);           // LCAP

    cg::cluster_group cl = cg::this_cluster();
    const int rank = (int)cl.block_rank();
    const int b    = blockIdx.x / CLSZ;
    const int tid  = threadIdx.x;
    const int lane = tid & 31;
    const int wid  = tid >> 5;
    const float OME = 1.0f - EPSV;

    const int r0 = rank * ROWS_PER_CTA;
    const int kbase = g_rowptr[r0];
    int kend = g_rowptr[r0 + ROWS_PER_CTA];
    if (kend - kbase > LCAP) kend = kbase + LCAP;
    const int cnt = kend - kbase;

    // ---- prologue ----
    for (int k = tid; k < cnt; k += NTH) {
        s_lin[k]  = (unsigned short)(g_lin[kbase + k] & (Ndim - 1));
        s_perm[k] = g_perm[kbase + k];
        s_rowC[k] = g_rowC[kbase + k];
        s_msgs[k] = 0.0f;
    }
    for (int j = tid; j <= Ndim; j += NTH)
        s_cptr[j] = (unsigned short)g_colptr[rank * (Ndim + 1) + j];
    if (tid <= ROWS_PER_CTA) s_rpt[tid] = g_rowptr[r0 + tid] - kbase;
    if (tid < ROWS_PER_CTA) {
        int row = r0 + tid;
        s_sign2[tid] = 2.0f * (1.0f - 2.0f * (float)synd[b * Mdim + row]);
        int d = g_rowptr[row + 1] - g_rowptr[row];
        s_offf[tid] = powf(OME, (float)(Ndim - d));
    }
    if (tid < COLS_PER_CTA)
        s_err[tid] = 1.0f - (float)errs[b * Ndim + rank * COLS_PER_CTA + tid];
    if (tid < Lnum) { s_resw[tid] = resw[tid]; s_rho[tid] = g_rho[tid]; }
    for (int j = tid; j < Ndim; j += NTH)
        s_colC[j] = llrs[j] * wllr[j];     // layer-0 combined column input
    __syncthreads();

    float acc = 0.0f;
    for (int l = 0; l < Lnum; l++) {
        const float rw = s_resw[l];
        const bool last = (l == Lnum - 1);
        const float* wmC = &g_mwdeC[l * CAP + kbase];          // CSC order
        const float* wnC = &g_wdeC[(last ? l : l + 1) * CAP + kbase];
        const int parW = l & 1;            // parity written this layer
        const int parR = (l - 1) & 1;      // parity read in combine (l>0)

        // ---- combine phase (l>0): read peers' parity-(l-1) partials ----
        if (l > 0) {
            if (tid < Ndim / 4) {
                // colC for all N (float4 per thread)
                const int f4 = tid;
                const int j = f4 * 4;
                float4 lv = ((const float4*)llrs)[f4];
                float4 wv = ((const float4*)(wllr + (size_t)l * Ndim))[f4];
                float4 s;
                s.x = lv.x * wv.x; s.y = lv.y * wv.y;
                s.z = lv.z * wv.z; s.w = lv.w * wv.w;
                float* basep = s_colP + parR * Ndim;
                #pragma unroll
                for (int r = 0; r < CLSZ; r++) {
                    float4 p = ((const float4*)cl.map_shared_rank(basep, r))[f4];
                    s.x += p.x; s.y += p.y; s.z += p.z; s.w += p.w;
                }
                ((float4*)s_colC)[f4] = s;
            } else if (tid < Ndim / 4 + 128) {
                // belief combine for owned slice + loss of layer l-1
                const int f4l = tid - Ndim / 4;            // 0..127
                const int f4 = rank * 128 + f4l;
                const int j = f4 * 4;
                float4 lv = ((const float4*)llrs)[f4];
                float4 wv = ((const float4*)(mwllr + (size_t)(l - 1) * Ndim))[f4];
                float4 x;
                x.x = lv.x * wv.x; x.y = lv.y * wv.y;
                x.z = lv.z * wv.z; x.w = lv.w * wv.w;
                float* basep = s_belP + parR * Ndim;
                #pragma unroll
                for (int r = 0; r < CLSZ; r++) {
                    float4 p = ((const float4*)cl.map_shared_rank(basep, r))[f4];
                    x.x += p.x; x.y += p.y; x.z += p.z; x.w += p.w;
                }
                const int jj = f4l * 4;
                float ls = 0.0f;
                ls += fmaxf(x.x, 0.0f) + log1pf(__expf(-fabsf(x.x))) - s_err[jj]     * x.x;
                ls += fmaxf(x.y, 0.0f) + log1pf(__expf(-fabsf(x.y))) - s_err[jj + 1] * x.y;
                ls += fmaxf(x.z, 0.0f) + log1pf(__expf(-fabsf(x.z))) - s_err[jj + 2] * x.z;
                ls += fmaxf(x.w, 0.0f) + log1pf(__expf(-fabsf(x.w))) - s_err[jj + 3] * x.w;
                acc += s_rho[l - 1] * ls;
            }
            __syncthreads();
        }

        // ---- phase A: entry-parallel tanh ----
        for (int k = tid; k < cnt; k += NTH) {
            float men = fminf(s_colC[s_lin[k]] - s_msgs[k], 80.0f);
            float t = __expf(men);
            float d = __fdividef(t - 1.0f, t + 1.0f);   // tanh(men/2)
            if (d == 0.0f) d = 1.0f;
            d = fminf(fmaxf(d, -OME), OME);
            s_d[k] = d;
        }
        __syncthreads();

        // ---- phase B: thread-per-row product over contiguous s_d ----
        if (tid < ROWS_PER_CTA) {
            int st = s_rpt[tid], en = s_rpt[tid + 1];
            float p0 = 1.0f, p1 = 1.0f;
            int k = st;
            for (; k + 1 < en; k += 2) { p0 *= s_d[k]; p1 *= s_d[k + 1]; }
            if (k < en) p0 *= s_d[k];
            s_rp[tid] = p0 * p1 * s_offf[tid];
        }
        __syncthreads();

        // ---- phase C: CSC pass — message update + partial col/bel sums ----
        for (int j = tid; j < Ndim; j += NTH) {
            int st = s_cptr[j], en = s_cptr[j + 1];
            float cs = 0.0f, bs = 0.0f;
            for (int t = st; t < en; t++) {
                int p = s_perm[t];
                int i = s_rowC[t];
                float d = s_d[p];
                float r = __fdividef(s_rp[i], d);
                float ath = (fabsf(r) < 6.25e-3f) ? r * (1.0f + (1.0f / 3.0f) * r * r)
                                                  : atanhf(r);
                float mn = ath * s_sign2[i] + rw * s_msgs[p];
                s_msgs[p] = mn;
                bs += mn * wmC[t];
                cs += mn * wnC[t];
            }
            s_belP[parW * Ndim + j] = bs;
            s_colP[parW * Ndim + j] = cs;
        }
        cl.sync();
    }

    // ---- tail: belief combine + loss for the final layer (parity 1) ----
    {
        const int parR = (Lnum - 1) & 1;
        if (tid >= Ndim / 4 && tid < Ndim / 4 + 128) {
            const int f4l = tid - Ndim / 4;
            const int f4 = rank * 128 + f4l;
            float4 lv = ((const float4*)llrs)[f4];
            float4 wv = ((const float4*)(mwllr + (size_t)(Lnum - 1) * Ndim))[f4];
            float4 x;
            x.x = lv.x * wv.x; x.y = lv.y * wv.y;
            x.z = lv.z * wv.z; x.w = lv.w * wv.w;
            float* basep = s_belP + parR * Ndim;
            #pragma unroll
            for (int r = 0; r < CLSZ; r++) {
                float4 p = ((const float4*)cl.map_shared_rank(basep, r))[f4];
                x.x += p.x; x.y += p.y; x.z += p.z; x.w += p.w;
            }
            const int jj = f4l * 4;
            float ls = 0.0f;
            ls += fmaxf(x.x, 0.0f) + log1pf(__expf(-fabsf(x.x))) - s_err[jj]     * x.x;
            ls += fmaxf(x.y, 0.0f) + log1pf(__expf(-fabsf(x.y))) - s_err[jj + 1] * x.y;
            ls += fmaxf(x.z, 0.0f) + log1pf(__expf(-fabsf(x.z))) - s_err[jj + 2] * x.z;
            ls += fmaxf(x.w, 0.0f) + log1pf(__expf(-fabsf(x.w))) - s_err[jj + 3] * x.w;
            acc += s_rho[Lnum - 1] * ls;
        }
        cl.sync();   // no CTA exits while peers still read its smem
    }

    // ---- loss reduce: acc lives in warps 16..19 (threads 512..639) ----
    for (int o = 16; o; o >>= 1) acc += __shfl_xor_sync(0xffffffffu, acc, o);
    if (wid >= 16 && wid < 20 && lane == 0) s_lacc[wid - 16] = acc;
    __syncthreads();
    if (tid == 0) {
        float s = s_lacc[0] + s_lacc[1] + s_lacc[2] + s_lacc[3];
        atomicAdd(out, s * (1.0f / (float)Bsz));
    }
}

// ---------------- host launcher ----------------
extern "C" void kernel_launch(void* const* d_in, const int* in_sizes, int n_in,
                              void* d_out, int out_size) {
    const int*   synd  = (const int*)d_in[0];
    const int*   errs  = (const int*)d_in[1];
    const float* H     = (const float*)d_in[2];
    const float* llrs  = (const float*)d_in[3];
    const float* wde   = (const float*)d_in[4];
    const float* wllr  = (const float*)d_in[5];
    const float* mwde  = (const float*)d_in[6];
    const float* mwllr = (const float*)d_in[7];
    const float* rhos  = (const float*)d_in[8];
    const float* resw  = (const float*)d_in[9];
    float* out = (float*)d_out;

    cudaFuncSetAttribute(k_main, cudaFuncAttributeMaxDynamicSharedMemorySize, SMEM_BYTES);

    k_prep1<<<Mdim, 512>>>((const float4*)H);
    k_prep2<<<1, Mdim>>>(rhos, out);
    k_prep3<<<CLSZ, 1024>>>();
    k_gather<<<(Lnum * CAP + 1023) / 1024, 1024>>>(wde, mwde);
    k_main<<<Bsz * CLSZ, NTH, SMEM_BYTES>>>(synd, errs, llrs, wllr, mwllr, resw, out);
}